// round 10
// baseline (speedup 1.0000x reference)
#include <cuda_runtime.h>

#define NN 100000
#define EE 800000
#define FULL 0xffffffffu
#define NB1 391            // ceil(NN/256)

typedef unsigned long long u64t;

// ---- f32x2 packed-math helpers ----
__device__ __forceinline__ u64t pk2(float lo, float hi) {
    u64t r; asm("mov.b64 %0, {%1, %2};" : "=l"(r) : "f"(lo), "f"(hi)); return r;
}
__device__ __forceinline__ void up2(float& lo, float& hi, u64t v) {
    asm("mov.b64 {%0, %1}, %2;" : "=f"(lo), "=f"(hi) : "l"(v));
}
__device__ __forceinline__ u64t fma2_(u64t a, u64t b, u64t c) {
    u64t d; asm("fma.rn.f32x2 %0, %1, %2, %3;" : "=l"(d) : "l"(a), "l"(b), "l"(c)); return d;
}
__device__ __forceinline__ u64t mul2_(u64t a, u64t b) {
    u64t d; asm("mul.rn.f32x2 %0, %1, %2;" : "=l"(d) : "l"(a), "l"(b)); return d;
}
__device__ __forceinline__ u64t add2_(u64t a, u64t b) {
    u64t d; asm("add.rn.f32x2 %0, %1, %2;" : "=l"(d) : "l"(a), "l"(b)); return d;
}
__device__ __forceinline__ float c4(const float4 v, int k) {
    return k == 0 ? v.x : k == 1 ? v.y : k == 2 ? v.z : v.w;
}

// ---------------- device scratch ----------------
__device__ float g_key[NN * 128];
__device__ float g_query[NN * 128];
__device__ float g_value[NN * 128];
__device__ float g_aggr[NN * 128];
__device__ float g_G[NN * 64];
__device__ float g_denom[NN * 4];
__device__ float g_wrbf[42 * 32];
__device__ float g_wsbf[16 * 32];
__device__ int   g_hist[NN];
__device__ int   g_cursor[NN];
__device__ int   g_blocksum[512];
__device__ int   g_perm[EE];

// ---------------- K0: fold weight pairs ----------------
__global__ void combine_weights_kernel(const float* __restrict__ w_rbf0,
                                       const float* __restrict__ w_rbf1,
                                       const float* __restrict__ w_sbf0,
                                       const float* __restrict__ w_sbf1)
{
    int t = blockIdx.x * blockDim.x + threadIdx.x;
    if (t < 42 * 32) {
        int i = t >> 5, o = t & 31;
        float s = 0.f;
        #pragma unroll
        for (int k = 0; k < 32; k++) s = fmaf(w_rbf0[i * 32 + k], w_rbf1[k * 32 + o], s);
        g_wrbf[t] = s;
    }
    if (t < 16 * 32) {
        int i = t >> 5, o = t & 31;
        float s = 0.f;
        #pragma unroll
        for (int k = 0; k < 32; k++) s = fmaf(w_sbf0[i * 32 + k], w_sbf1[k * 32 + o], s);
        g_wsbf[t] = s;
    }
}

// ---------------- counting sort of edges by dst ----------------
__global__ void hist_kernel(const int* __restrict__ ei)
{
    int t = blockIdx.x * blockDim.x + threadIdx.x;
    int n = gridDim.x * blockDim.x;
    for (int e = t; e < EE; e += n) atomicAdd(&g_hist[__ldg(ei + EE + e)], 1);
}

__global__ void scan1_kernel()
{
    __shared__ int wsum[8];
    int idx = blockIdx.x * 256 + threadIdx.x;
    int lane = threadIdx.x & 31, w = threadIdx.x >> 5;
    int v = (idx < NN) ? g_hist[idx] : 0;
    int x = v;
    #pragma unroll
    for (int o = 1; o < 32; o <<= 1) {
        int y = __shfl_up_sync(FULL, x, o);
        if (lane >= o) x += y;
    }
    if (lane == 31) wsum[w] = x;
    __syncthreads();
    if (w == 0) {
        int s = (lane < 8) ? wsum[lane] : 0;
        #pragma unroll
        for (int o = 1; o < 8; o <<= 1) {
            int y = __shfl_up_sync(FULL, s, o);
            if (lane >= o) s += y;
        }
        if (lane < 8) wsum[lane] = s;
    }
    __syncthreads();
    int woff = (w > 0) ? wsum[w - 1] : 0;
    if (idx < NN) g_cursor[idx] = x - v + woff;
    if (threadIdx.x == 255) g_blocksum[blockIdx.x] = wsum[7];
}

__global__ void scan2_kernel()
{
    __shared__ int sm2[512];
    int t = threadIdx.x;
    int v = (t < NB1) ? g_blocksum[t] : 0;
    sm2[t] = v;
    __syncthreads();
    #pragma unroll
    for (int o = 1; o < 512; o <<= 1) {
        int y = 0;
        if (t >= o) y = sm2[t - o];
        __syncthreads();
        sm2[t] += y;
        __syncthreads();
    }
    if (t < NB1) g_blocksum[t] = sm2[t] - v;   // exclusive
}

__global__ void scan3_kernel()
{
    int idx = blockIdx.x * 256 + threadIdx.x;
    if (idx < NN) g_cursor[idx] += g_blocksum[idx >> 8];
}

__global__ void scatter_kernel(const int* __restrict__ ei)
{
    int t = blockIdx.x * blockDim.x + threadIdx.x;
    int n = gridDim.x * blockDim.x;
    for (int e = t; e < EE; e += n) {
        int d = __ldg(ei + EE + e);
        int pos = atomicAdd(&g_cursor[d], 1);
        g_perm[pos] = e;
    }
}

// ---------------- K1: per-node K/Q/V/skip + G, 4 nodes per warp iter ----------------
__global__ __launch_bounds__(256, 2)
void node_kernel(const float* __restrict__ x, const float* __restrict__ rbf,
                 const float* __restrict__ w_ek,
                 const float* __restrict__ w_k, const float* __restrict__ b_k,
                 const float* __restrict__ w_q, const float* __restrict__ b_q,
                 const float* __restrict__ w_v, const float* __restrict__ b_v,
                 const float* __restrict__ w_skip, const float* __restrict__ b_skip,
                 float* __restrict__ out)
{
    extern __shared__ float sm[];
    float* sw_k    = sm;
    float* sw_q    = sm + 4096;
    float* sw_v    = sm + 8192;
    float* sw_s    = sm + 12288;
    float* sw_ek   = sm + 16384;
    float* sw_rbfc = sm + 18432;
    float* sb      = sm + 19776;

    for (int i = threadIdx.x; i < 4096; i += blockDim.x) {
        sw_k[i] = w_k[i]; sw_q[i] = w_q[i]; sw_v[i] = w_v[i]; sw_s[i] = w_skip[i];
    }
    for (int i = threadIdx.x; i < 2048; i += blockDim.x) sw_ek[i] = w_ek[i];
    for (int i = threadIdx.x; i < 1344; i += blockDim.x) sw_rbfc[i] = g_wrbf[i];
    for (int i = threadIdx.x; i < 128; i += blockDim.x) {
        sb[i] = b_k[i]; sb[128 + i] = b_q[i]; sb[256 + i] = b_v[i]; sb[384 + i] = b_skip[i];
    }
    __syncthreads();

    int lane = threadIdx.x & 31;
    int r = lane & 7;
    int gw = (blockIdx.x * blockDim.x + threadIdx.x) >> 5;
    int nw = (gridDim.x * blockDim.x) >> 5;

    for (int n0 = gw * 4; n0 < NN; n0 += nw * 4) {
        float f[4] = {0.f, 0.f, 0.f, 0.f};
        const float* rn = rbf + (size_t)n0 * 42;
        #pragma unroll 6
        for (int i = 0; i < 42; i++) {
            float w = sw_rbfc[i * 32 + lane];
            f[0] = fmaf(__ldg(rn + i),       w, f[0]);
            f[1] = fmaf(__ldg(rn + 42 + i),  w, f[1]);
            f[2] = fmaf(__ldg(rn + 84 + i),  w, f[2]);
            f[3] = fmaf(__ldg(rn + 126 + i), w, f[3]);
        }
        float xv[4], xs[4];
        #pragma unroll
        for (int j = 0; j < 4; j++) {
            xv[j] = __ldg(x + (size_t)(n0 + j) * 32 + lane);
            xs[j] = f[j] * xv[j];
        }

        ulonglong2 bK = *(const ulonglong2*)(sb + 4 * lane);
        ulonglong2 bQ = *(const ulonglong2*)(sb + 128 + 4 * lane);
        ulonglong2 bV = *(const ulonglong2*)(sb + 256 + 4 * lane);
        ulonglong2 bS = *(const ulonglong2*)(sb + 384 + 4 * lane);
        u64t aK[4][2], aQ[4][2], aV[4][2], aS[4][2];
        #pragma unroll
        for (int j = 0; j < 4; j++) {
            aK[j][0] = bK.x; aK[j][1] = bK.y;
            aQ[j][0] = bQ.x; aQ[j][1] = bQ.y;
            aV[j][0] = bV.x; aV[j][1] = bV.y;
            aS[j][0] = bS.x; aS[j][1] = bS.y;
        }

        #pragma unroll 8
        for (int c = 0; c < 32; c++) {
            ulonglong2 wk = *(const ulonglong2*)(sw_k + c * 128 + 4 * lane);
            ulonglong2 wq = *(const ulonglong2*)(sw_q + c * 128 + 4 * lane);
            ulonglong2 wv = *(const ulonglong2*)(sw_v + c * 128 + 4 * lane);
            ulonglong2 ws = *(const ulonglong2*)(sw_s + c * 128 + 4 * lane);
            #pragma unroll
            for (int j = 0; j < 4; j++) {
                float ms = __shfl_sync(FULL, xs[j], c);
                float mx = __shfl_sync(FULL, xv[j], c);
                u64t pms = pk2(ms, ms);
                u64t pmx = pk2(mx, mx);
                aK[j][0] = fma2_(pms, wk.x, aK[j][0]); aK[j][1] = fma2_(pms, wk.y, aK[j][1]);
                aQ[j][0] = fma2_(pmx, wq.x, aQ[j][0]); aQ[j][1] = fma2_(pmx, wq.y, aQ[j][1]);
                aV[j][0] = fma2_(pms, wv.x, aV[j][0]); aV[j][1] = fma2_(pms, wv.y, aV[j][1]);
                aS[j][0] = fma2_(pmx, ws.x, aS[j][0]); aS[j][1] = fma2_(pmx, ws.y, aS[j][1]);
            }
        }

        #pragma unroll
        for (int j = 0; j < 4; j++) {
            ulonglong2 o;
            o.x = aK[j][0]; o.y = aK[j][1];
            *(ulonglong2*)(g_key   + (size_t)(n0 + j) * 128 + 4 * lane) = o;
            o.x = aQ[j][0]; o.y = aQ[j][1];
            *(ulonglong2*)(g_query + (size_t)(n0 + j) * 128 + 4 * lane) = o;
            o.x = aV[j][0]; o.y = aV[j][1];
            *(ulonglong2*)(g_value + (size_t)(n0 + j) * 128 + 4 * lane) = o;
            o.x = aS[j][0]; o.y = aS[j][1];
            *(ulonglong2*)(out     + (size_t)(n0 + j) * 128 + 4 * lane) = o;
        }

        float4 q[4];
        #pragma unroll
        for (int j = 0; j < 4; j++) {
            up2(q[j].x, q[j].y, aQ[j][0]);
            up2(q[j].z, q[j].w, aQ[j][1]);
        }
        float G0[4] = {0.f,0.f,0.f,0.f}, G1[4] = {0.f,0.f,0.f,0.f};
        #pragma unroll
        for (int i = 0; i < 16; i++) {
            float4 we = *(const float4*)(sw_ek + i * 128 + 4 * lane);
            #pragma unroll
            for (int j = 0; j < 4; j++) {
                float p = we.x * q[j].x + we.y * q[j].y + we.z * q[j].z + we.w * q[j].w;
                p += __shfl_xor_sync(FULL, p, 1);
                p += __shfl_xor_sync(FULL, p, 2);
                p += __shfl_xor_sync(FULL, p, 4);
                if ((i >> 1) == r) { if (i & 1) G1[j] = p; else G0[j] = p; }
            }
        }
        #pragma unroll
        for (int j = 0; j < 4; j++)
            *(float2*)(g_G + (size_t)(n0 + j) * 64 + (lane >> 3) * 16 + 2 * r)
                = make_float2(G0[j], G1[j]);
    }
}

// ---------------- K2: dst-sorted edge pass with run accumulation ----------------
#define FLUSH_ACC() do { if (dcur >= 0) { \
    float4 mm; up2(mm.x, mm.y, accL); up2(mm.z, mm.w, accH); \
    atomicAdd((float4*)(g_aggr + (size_t)dcur * 128 + 4 * lane), mm); \
    if (r == 0) atomicAdd(g_denom + (size_t)dcur * 4 + h, accD); \
    accL = 0; accH = 0; accD = 0.f; } } while (0)

__global__ __launch_bounds__(128, 4)
void edge_kernel(const float* __restrict__ edge_attr, const float* __restrict__ sbf,
                 const float* __restrict__ w_ev, const int* __restrict__ ei)
{
    __shared__ __align__(16) float sw_ev[2048];
    __shared__ __align__(16) float sw_sf[512];
    for (int i = threadIdx.x; i < 2048; i += blockDim.x) sw_ev[i] = w_ev[i];
    for (int i = threadIdx.x; i < 512; i += blockDim.x) sw_sf[i] = g_wsbf[i];
    __syncthreads();

    int lane = threadIdx.x & 31;
    int r = lane & 7;
    int h = lane >> 3;
    int gw = (blockIdx.x * blockDim.x + threadIdx.x) >> 5;   // 0..3999
    const int CHUNK = 200;                                   // 4000 * 200 == EE
    int base = gw * CHUNK;
    const float inv_sqrt_c = 0.17677669529663687f;

    u64t accL = 0, accH = 0;
    float accD = 0.f;
    int dcur = -1;

    for (int i = base; i < base + CHUNK; i += 2) {
        int e0 = __ldg(g_perm + i);
        int e1 = __ldg(g_perm + i + 1);
        int s0 = __ldg(ei + e0);
        int s1 = __ldg(ei + e1);
        int d0 = __ldg(ei + EE + e0);
        int d1 = __ldg(ei + EE + e1);

        const float4* eap0 = (const float4*)(edge_attr + (size_t)e0 * 16);
        const float4* eap1 = (const float4*)(edge_attr + (size_t)e1 * 16);
        float4 ea0[4], ea1[4];
        #pragma unroll
        for (int j = 0; j < 4; j++) { ea0[j] = __ldg(eap0 + j); ea1[j] = __ldg(eap1 + j); }
        float eav0 = __ldg(edge_attr + (size_t)e0 * 16 + (lane & 15));
        float eav1 = __ldg(edge_attr + (size_t)e1 * 16 + (lane & 15));

        // edge_val GEMV, f32x2
        u64t ev0l = 0, ev0h = 0, ev1l = 0, ev1h = 0;
        #pragma unroll
        for (int j = 0; j < 16; j++) {
            float a0 = c4(ea0[j >> 2], j & 3);
            float a1 = c4(ea1[j >> 2], j & 3);
            ulonglong2 w = *(const ulonglong2*)(sw_ev + j * 128 + 4 * lane);
            u64t pa0 = pk2(a0, a0);
            u64t pa1 = pk2(a1, a1);
            ev0l = fma2_(pa0, w.x, ev0l); ev0h = fma2_(pa0, w.y, ev0h);
            ev1l = fma2_(pa1, w.x, ev1l); ev1h = fma2_(pa1, w.y, ev1h);
        }

        // gathers (q/G dst-sorted -> cache hits)
        ulonglong2 k0 = *(const ulonglong2*)(g_key   + (size_t)s0 * 128 + 4 * lane);
        ulonglong2 k1 = *(const ulonglong2*)(g_key   + (size_t)s1 * 128 + 4 * lane);
        ulonglong2 q0 = *(const ulonglong2*)(g_query + (size_t)d0 * 128 + 4 * lane);
        ulonglong2 q1 = *(const ulonglong2*)(g_query + (size_t)d1 * 128 + 4 * lane);
        ulonglong2 v0 = *(const ulonglong2*)(g_value + (size_t)s0 * 128 + 4 * lane);
        ulonglong2 v1 = *(const ulonglong2*)(g_value + (size_t)s1 * 128 + 4 * lane);
        float2 Ga = *(const float2*)(g_G + (size_t)d0 * 64 + h * 16 + 2 * r);
        float2 Gb = *(const float2*)(g_G + (size_t)d1 * 64 + h * 16 + 2 * r);

        // alpha
        float e00 = __shfl_sync(FULL, eav0, 2 * r);
        float e01 = __shfl_sync(FULL, eav0, 2 * r + 1);
        float e10 = __shfl_sync(FULL, eav1, 2 * r);
        float e11 = __shfl_sync(FULL, eav1, 2 * r + 1);
        u64t t0 = fma2_(q0.x, k0.x, mul2_(q0.y, k0.y));
        u64t t1 = fma2_(q1.x, k1.x, mul2_(q1.y, k1.y));
        float tl, th;
        up2(tl, th, t0);
        float p0 = tl + th + e00 * Ga.x + e01 * Ga.y;
        up2(tl, th, t1);
        float p1 = tl + th + e10 * Gb.x + e11 * Gb.y;
        p0 += __shfl_xor_sync(FULL, p0, 1);
        p0 += __shfl_xor_sync(FULL, p0, 2);
        p0 += __shfl_xor_sync(FULL, p0, 4);
        p1 += __shfl_xor_sync(FULL, p1, 1);
        p1 += __shfl_xor_sync(FULL, p1, 2);
        p1 += __shfl_xor_sync(FULL, p1, 4);
        float ex0 = __expf(p0 * inv_sqrt_c);
        float ex1 = __expf(p1 * inv_sqrt_c);

        // sbf slices for this lane's head
        const float4* sp0 = (const float4*)(sbf + (size_t)e0 * 64 + h * 16);
        const float4* sp1 = (const float4*)(sbf + (size_t)e1 * 64 + h * 16);
        float4 sb0[4], sb1[4];
        #pragma unroll
        for (int j = 0; j < 4; j++) { sb0[j] = __ldg(sp0 + j); sb1[j] = __ldg(sp1 + j); }

        u64t sf0l = 0, sf0h = 0, sf1l = 0, sf1h = 0;
        #pragma unroll
        for (int j = 0; j < 16; j++) {
            float a0 = c4(sb0[j >> 2], j & 3);
            float a1 = c4(sb1[j >> 2], j & 3);
            ulonglong2 w = *(const ulonglong2*)(sw_sf + j * 32 + 4 * r);
            u64t pa0 = pk2(a0, a0);
            u64t pa1 = pk2(a1, a1);
            sf0l = fma2_(pa0, w.x, sf0l); sf0h = fma2_(pa0, w.y, sf0h);
            sf1l = fma2_(pa1, w.x, sf1l); sf1h = fma2_(pa1, w.y, sf1h);
        }

        u64t pex0 = pk2(ex0, ex0);
        u64t pex1 = pk2(ex1, ex1);
        u64t m0l = mul2_(mul2_(add2_(v0.x, ev0l), sf0l), pex0);
        u64t m0h = mul2_(mul2_(add2_(v0.y, ev0h), sf0h), pex0);
        u64t m1l = mul2_(mul2_(add2_(v1.x, ev1l), sf1l), pex1);
        u64t m1h = mul2_(mul2_(add2_(v1.y, ev1h), sf1h), pex1);

        // run accumulation (dst-sorted; branch is warp-uniform)
        if (d0 != dcur) { FLUSH_ACC(); dcur = d0; }
        accL = add2_(accL, m0l); accH = add2_(accH, m0h); accD += ex0;
        if (d1 != dcur) { FLUSH_ACC(); dcur = d1; }
        accL = add2_(accL, m1l); accH = add2_(accH, m1h); accD += ex1;
    }
    FLUSH_ACC();
}

// ---------------- K3: normalize + add skip ----------------
__global__ __launch_bounds__(256)
void finalize_kernel(float* __restrict__ out)
{
    int t = blockIdx.x * blockDim.x + threadIdx.x;
    if (t >= NN * 32) return;
    int n = t >> 5;
    int g = t & 31;
    float d = g_denom[n * 4 + (g >> 3)];
    float inv = (d > 0.f) ? 1.0f / d : 0.f;
    float4 a = *(const float4*)(g_aggr + n * 128 + 4 * g);
    float4 o = *(const float4*)(out + n * 128 + 4 * g);
    o.x = fmaf(a.x, inv, o.x);
    o.y = fmaf(a.y, inv, o.y);
    o.z = fmaf(a.z, inv, o.z);
    o.w = fmaf(a.w, inv, o.w);
    *(float4*)(out + n * 128 + 4 * g) = o;
}

// ---------------- host ----------------
extern "C" void kernel_launch(void* const* d_in, const int* in_sizes, int n_in,
                              void* d_out, int out_size)
{
    const float* x         = (const float*)d_in[0];
    const float* edge_attr = (const float*)d_in[1];
    const float* rbf       = (const float*)d_in[2];
    const float* sbf       = (const float*)d_in[3];
    const float* w_rbf0    = (const float*)d_in[4];
    const float* w_rbf1    = (const float*)d_in[5];
    const float* w_sbf0    = (const float*)d_in[6];
    const float* w_sbf1    = (const float*)d_in[7];
    const float* w_ek      = (const float*)d_in[8];
    const float* w_ev      = (const float*)d_in[9];
    const float* w_k       = (const float*)d_in[10];
    const float* b_k       = (const float*)d_in[11];
    const float* w_q       = (const float*)d_in[12];
    const float* b_q       = (const float*)d_in[13];
    const float* w_v       = (const float*)d_in[14];
    const float* b_v       = (const float*)d_in[15];
    const float* w_skip    = (const float*)d_in[16];
    const float* b_skip    = (const float*)d_in[17];
    const int*   ei        = (const int*)d_in[18];
    float* out = (float*)d_out;

    void *p_aggr, *p_denom, *p_hist;
    cudaGetSymbolAddress(&p_aggr, g_aggr);
    cudaGetSymbolAddress(&p_denom, g_denom);
    cudaGetSymbolAddress(&p_hist, g_hist);
    cudaMemsetAsync(p_aggr, 0, (size_t)NN * 128 * sizeof(float));
    cudaMemsetAsync(p_denom, 0, (size_t)NN * 4 * sizeof(float));
    cudaMemsetAsync(p_hist, 0, (size_t)NN * sizeof(int));

    combine_weights_kernel<<<6, 256>>>(w_rbf0, w_rbf1, w_sbf0, w_sbf1);

    // counting sort of edges by dst
    hist_kernel<<<592, 256>>>(ei);
    scan1_kernel<<<NB1, 256>>>();
    scan2_kernel<<<1, 512>>>();
    scan3_kernel<<<NB1, 256>>>();
    scatter_kernel<<<592, 256>>>(ei);

    int smem = 20288 * (int)sizeof(float);  // 81152 B -> 2 CTA/SM
    cudaFuncSetAttribute(node_kernel, cudaFuncAttributeMaxDynamicSharedMemorySize, smem);
    node_kernel<<<296, 256, smem>>>(x, rbf, w_ek, w_k, b_k, w_q, b_q,
                                    w_v, b_v, w_skip, b_skip, out);

    edge_kernel<<<1000, 128>>>(edge_attr, sbf, w_ev, ei);

    finalize_kernel<<<(NN * 32 + 255) / 256, 256>>>(out);
}

// round 11
// speedup vs baseline: 1.1063x; 1.1063x over previous
#include <cuda_runtime.h>

#define NN 100000
#define EE 800000
#define FULL 0xffffffffu

typedef unsigned long long u64t;

// ---- f32x2 packed-math helpers (Blackwell FFMA2 path, PTX-only) ----
__device__ __forceinline__ u64t pk2(float lo, float hi) {
    u64t r; asm("mov.b64 %0, {%1, %2};" : "=l"(r) : "f"(lo), "f"(hi)); return r;
}
__device__ __forceinline__ void up2(float& lo, float& hi, u64t v) {
    asm("mov.b64 {%0, %1}, %2;" : "=f"(lo), "=f"(hi) : "l"(v));
}
__device__ __forceinline__ u64t fma2_(u64t a, u64t b, u64t c) {
    u64t d; asm("fma.rn.f32x2 %0, %1, %2, %3;" : "=l"(d) : "l"(a), "l"(b), "l"(c)); return d;
}
__device__ __forceinline__ u64t mul2_(u64t a, u64t b) {
    u64t d; asm("mul.rn.f32x2 %0, %1, %2;" : "=l"(d) : "l"(a), "l"(b)); return d;
}
__device__ __forceinline__ u64t add2_(u64t a, u64t b) {
    u64t d; asm("add.rn.f32x2 %0, %1, %2;" : "=l"(d) : "l"(a), "l"(b)); return d;
}
__device__ __forceinline__ float c4(const float4 v, int k) {
    return k == 0 ? v.x : k == 1 ? v.y : k == 2 ? v.z : v.w;
}

// ---------------- device scratch (no allocs allowed) ----------------
__device__ float g_kv[NN * 256];     // [n][0:128)=key, [n][128:256)=value (one 1KB record per node)
__device__ float g_query[NN * 128];
__device__ float g_aggr[NN * 128];
__device__ float g_G[NN * 64];
__device__ float g_denom[NN * 4];
__device__ float g_wrbf[42 * 32];
__device__ float g_wsbf[16 * 32];

// ---------------- K0: fold weight pairs ----------------
__global__ void combine_weights_kernel(const float* __restrict__ w_rbf0,
                                       const float* __restrict__ w_rbf1,
                                       const float* __restrict__ w_sbf0,
                                       const float* __restrict__ w_sbf1)
{
    int t = blockIdx.x * blockDim.x + threadIdx.x;
    if (t < 42 * 32) {
        int i = t >> 5, o = t & 31;
        float s = 0.f;
        #pragma unroll
        for (int k = 0; k < 32; k++) s = fmaf(w_rbf0[i * 32 + k], w_rbf1[k * 32 + o], s);
        g_wrbf[t] = s;
    }
    if (t < 16 * 32) {
        int i = t >> 5, o = t & 31;
        float s = 0.f;
        #pragma unroll
        for (int k = 0; k < 32; k++) s = fmaf(w_sbf0[i * 32 + k], w_sbf1[k * 32 + o], s);
        g_wsbf[t] = s;
    }
}

// ---------------- dummy: aligns ncu -s 5 onto edge_kernel ----------------
__global__ void profile_align_kernel() {}

// ---------------- K1: per-node K/Q/V/skip + G, 4 nodes per warp iter ----------------
__global__ __launch_bounds__(256, 2)
void node_kernel(const float* __restrict__ x, const float* __restrict__ rbf,
                 const float* __restrict__ w_ek,
                 const float* __restrict__ w_k, const float* __restrict__ b_k,
                 const float* __restrict__ w_q, const float* __restrict__ b_q,
                 const float* __restrict__ w_v, const float* __restrict__ b_v,
                 const float* __restrict__ w_skip, const float* __restrict__ b_skip,
                 float* __restrict__ out)
{
    extern __shared__ float sm[];
    float* sw_k    = sm;
    float* sw_q    = sm + 4096;
    float* sw_v    = sm + 8192;
    float* sw_s    = sm + 12288;
    float* sw_ek   = sm + 16384;
    float* sw_rbfc = sm + 18432;
    float* sb      = sm + 19776;

    for (int i = threadIdx.x; i < 4096; i += blockDim.x) {
        sw_k[i] = w_k[i]; sw_q[i] = w_q[i]; sw_v[i] = w_v[i]; sw_s[i] = w_skip[i];
    }
    for (int i = threadIdx.x; i < 2048; i += blockDim.x) sw_ek[i] = w_ek[i];
    for (int i = threadIdx.x; i < 1344; i += blockDim.x) sw_rbfc[i] = g_wrbf[i];
    for (int i = threadIdx.x; i < 128; i += blockDim.x) {
        sb[i] = b_k[i]; sb[128 + i] = b_q[i]; sb[256 + i] = b_v[i]; sb[384 + i] = b_skip[i];
    }
    __syncthreads();

    int lane = threadIdx.x & 31;
    int r = lane & 7;
    int gw = (blockIdx.x * blockDim.x + threadIdx.x) >> 5;
    int nw = (gridDim.x * blockDim.x) >> 5;

    for (int n0 = gw * 4; n0 < NN; n0 += nw * 4) {
        float f[4] = {0.f, 0.f, 0.f, 0.f};
        const float* rn = rbf + (size_t)n0 * 42;
        #pragma unroll 6
        for (int i = 0; i < 42; i++) {
            float w = sw_rbfc[i * 32 + lane];
            f[0] = fmaf(__ldg(rn + i),       w, f[0]);
            f[1] = fmaf(__ldg(rn + 42 + i),  w, f[1]);
            f[2] = fmaf(__ldg(rn + 84 + i),  w, f[2]);
            f[3] = fmaf(__ldg(rn + 126 + i), w, f[3]);
        }
        float xv[4], xs[4];
        #pragma unroll
        for (int j = 0; j < 4; j++) {
            xv[j] = __ldg(x + (size_t)(n0 + j) * 32 + lane);
            xs[j] = f[j] * xv[j];
        }

        ulonglong2 bK = *(const ulonglong2*)(sb + 4 * lane);
        ulonglong2 bQ = *(const ulonglong2*)(sb + 128 + 4 * lane);
        ulonglong2 bV = *(const ulonglong2*)(sb + 256 + 4 * lane);
        ulonglong2 bS = *(const ulonglong2*)(sb + 384 + 4 * lane);
        u64t aK[4][2], aQ[4][2], aV[4][2], aS[4][2];
        #pragma unroll
        for (int j = 0; j < 4; j++) {
            aK[j][0] = bK.x; aK[j][1] = bK.y;
            aQ[j][0] = bQ.x; aQ[j][1] = bQ.y;
            aV[j][0] = bV.x; aV[j][1] = bV.y;
            aS[j][0] = bS.x; aS[j][1] = bS.y;
        }

        #pragma unroll 8
        for (int c = 0; c < 32; c++) {
            ulonglong2 wk = *(const ulonglong2*)(sw_k + c * 128 + 4 * lane);
            ulonglong2 wq = *(const ulonglong2*)(sw_q + c * 128 + 4 * lane);
            ulonglong2 wv = *(const ulonglong2*)(sw_v + c * 128 + 4 * lane);
            ulonglong2 ws = *(const ulonglong2*)(sw_s + c * 128 + 4 * lane);
            #pragma unroll
            for (int j = 0; j < 4; j++) {
                float ms = __shfl_sync(FULL, xs[j], c);
                float mx = __shfl_sync(FULL, xv[j], c);
                u64t pms = pk2(ms, ms);
                u64t pmx = pk2(mx, mx);
                aK[j][0] = fma2_(pms, wk.x, aK[j][0]); aK[j][1] = fma2_(pms, wk.y, aK[j][1]);
                aQ[j][0] = fma2_(pmx, wq.x, aQ[j][0]); aQ[j][1] = fma2_(pmx, wq.y, aQ[j][1]);
                aV[j][0] = fma2_(pms, wv.x, aV[j][0]); aV[j][1] = fma2_(pms, wv.y, aV[j][1]);
                aS[j][0] = fma2_(pmx, ws.x, aS[j][0]); aS[j][1] = fma2_(pmx, ws.y, aS[j][1]);
            }
        }

        #pragma unroll
        for (int j = 0; j < 4; j++) {
            ulonglong2 o;
            o.x = aK[j][0]; o.y = aK[j][1];
            *(ulonglong2*)(g_kv    + (size_t)(n0 + j) * 256 + 4 * lane) = o;        // key
            o.x = aV[j][0]; o.y = aV[j][1];
            *(ulonglong2*)(g_kv    + (size_t)(n0 + j) * 256 + 128 + 4 * lane) = o;  // value
            o.x = aQ[j][0]; o.y = aQ[j][1];
            *(ulonglong2*)(g_query + (size_t)(n0 + j) * 128 + 4 * lane) = o;
            o.x = aS[j][0]; o.y = aS[j][1];
            *(ulonglong2*)(out     + (size_t)(n0 + j) * 128 + 4 * lane) = o;
        }

        float4 q[4];
        #pragma unroll
        for (int j = 0; j < 4; j++) {
            up2(q[j].x, q[j].y, aQ[j][0]);
            up2(q[j].z, q[j].w, aQ[j][1]);
        }
        float G0[4] = {0.f,0.f,0.f,0.f}, G1[4] = {0.f,0.f,0.f,0.f};
        #pragma unroll
        for (int i = 0; i < 16; i++) {
            float4 we = *(const float4*)(sw_ek + i * 128 + 4 * lane);
            #pragma unroll
            for (int j = 0; j < 4; j++) {
                float p = we.x * q[j].x + we.y * q[j].y + we.z * q[j].z + we.w * q[j].w;
                p += __shfl_xor_sync(FULL, p, 1);
                p += __shfl_xor_sync(FULL, p, 2);
                p += __shfl_xor_sync(FULL, p, 4);
                if ((i >> 1) == r) { if (i & 1) G1[j] = p; else G0[j] = p; }
            }
        }
        #pragma unroll
        for (int j = 0; j < 4; j++)
            *(float2*)(g_G + (size_t)(n0 + j) * 64 + (lane >> 3) * 16 + 2 * r)
                = make_float2(G0[j], G1[j]);
    }
}

// ---------------- K2: edge pass, 2 edges/iter, shuffle-free GEMVs ----------------
__global__ __launch_bounds__(256, 2)
void edge_kernel(const float* __restrict__ edge_attr, const float* __restrict__ sbf,
                 const float* __restrict__ w_ev, const int* __restrict__ ei)
{
    __shared__ __align__(16) float sw_ev[2048];
    __shared__ __align__(16) float sw_sf[512];
    for (int i = threadIdx.x; i < 2048; i += blockDim.x) sw_ev[i] = w_ev[i];
    for (int i = threadIdx.x; i < 512; i += blockDim.x) sw_sf[i] = g_wsbf[i];
    __syncthreads();

    int lane = threadIdx.x & 31;
    int r = lane & 7;
    int h = lane >> 3;
    int gw = (blockIdx.x * blockDim.x + threadIdx.x) >> 5;
    int nw = (gridDim.x * blockDim.x) >> 5;
    const float inv_sqrt_c = 0.17677669529663687f;

    for (int e = gw * 2; e < EE; e += nw * 2) {
        int s0 = __ldg(ei + e);
        int s1 = __ldg(ei + e + 1);
        int d0 = __ldg(ei + EE + e);
        int d1 = __ldg(ei + EE + e + 1);

        const float4* eap = (const float4*)(edge_attr + (size_t)e * 16);
        float4 ea0[4], ea1[4];
        #pragma unroll
        for (int i = 0; i < 4; i++) { ea0[i] = __ldg(eap + i); ea1[i] = __ldg(eap + 4 + i); }
        float eav0 = __ldg(edge_attr + (size_t)e * 16 + (lane & 15));
        float eav1 = __ldg(edge_attr + (size_t)(e + 1) * 16 + (lane & 15));

        // edge_val GEMV, shuffle-free, f32x2
        u64t ev0l = 0, ev0h = 0, ev1l = 0, ev1h = 0;
        #pragma unroll
        for (int i = 0; i < 16; i++) {
            float a0 = c4(ea0[i >> 2], i & 3);
            float a1 = c4(ea1[i >> 2], i & 3);
            ulonglong2 w = *(const ulonglong2*)(sw_ev + i * 128 + 4 * lane);
            u64t pa0 = pk2(a0, a0);
            u64t pa1 = pk2(a1, a1);
            ev0l = fma2_(pa0, w.x, ev0l); ev0h = fma2_(pa0, w.y, ev0h);
            ev1l = fma2_(pa1, w.x, ev1l); ev1h = fma2_(pa1, w.y, ev1h);
        }

        // gathers: key+value share one 1KB record per src node
        ulonglong2 k0 = *(const ulonglong2*)(g_kv    + (size_t)s0 * 256 + 4 * lane);
        ulonglong2 v0 = *(const ulonglong2*)(g_kv    + (size_t)s0 * 256 + 128 + 4 * lane);
        ulonglong2 k1 = *(const ulonglong2*)(g_kv    + (size_t)s1 * 256 + 4 * lane);
        ulonglong2 v1 = *(const ulonglong2*)(g_kv    + (size_t)s1 * 256 + 128 + 4 * lane);
        ulonglong2 q0 = *(const ulonglong2*)(g_query + (size_t)d0 * 128 + 4 * lane);
        ulonglong2 q1 = *(const ulonglong2*)(g_query + (size_t)d1 * 128 + 4 * lane);
        float2 Ga = *(const float2*)(g_G + (size_t)d0 * 64 + h * 16 + 2 * r);
        float2 Gb = *(const float2*)(g_G + (size_t)d1 * 64 + h * 16 + 2 * r);

        // alpha
        float e00 = __shfl_sync(FULL, eav0, 2 * r);
        float e01 = __shfl_sync(FULL, eav0, 2 * r + 1);
        float e10 = __shfl_sync(FULL, eav1, 2 * r);
        float e11 = __shfl_sync(FULL, eav1, 2 * r + 1);
        u64t t0 = fma2_(q0.x, k0.x, mul2_(q0.y, k0.y));
        u64t t1 = fma2_(q1.x, k1.x, mul2_(q1.y, k1.y));
        float tl, th;
        up2(tl, th, t0);
        float p0 = tl + th + e00 * Ga.x + e01 * Ga.y;
        up2(tl, th, t1);
        float p1 = tl + th + e10 * Gb.x + e11 * Gb.y;
        p0 += __shfl_xor_sync(FULL, p0, 1);
        p0 += __shfl_xor_sync(FULL, p0, 2);
        p0 += __shfl_xor_sync(FULL, p0, 4);
        p1 += __shfl_xor_sync(FULL, p1, 1);
        p1 += __shfl_xor_sync(FULL, p1, 2);
        p1 += __shfl_xor_sync(FULL, p1, 4);
        float ex0 = __expf(p0 * inv_sqrt_c);
        float ex1 = __expf(p1 * inv_sqrt_c);
        if (r == 0) {
            atomicAdd(g_denom + (size_t)d0 * 4 + h, ex0);
            atomicAdd(g_denom + (size_t)d1 * 4 + h, ex1);
        }

        // sbf slices for this lane's head
        const float4* sp0 = (const float4*)(sbf + (size_t)e * 64 + h * 16);
        float4 sb0[4], sb1[4];
        #pragma unroll
        for (int i = 0; i < 4; i++) { sb0[i] = __ldg(sp0 + i); sb1[i] = __ldg(sp0 + 16 + i); }

        // sbf filter GEMV, shuffle-free, f32x2
        u64t sf0l = 0, sf0h = 0, sf1l = 0, sf1h = 0;
        #pragma unroll
        for (int i = 0; i < 16; i++) {
            float a0 = c4(sb0[i >> 2], i & 3);
            float a1 = c4(sb1[i >> 2], i & 3);
            ulonglong2 w = *(const ulonglong2*)(sw_sf + i * 32 + 4 * r);
            u64t pa0 = pk2(a0, a0);
            u64t pa1 = pk2(a1, a1);
            sf0l = fma2_(pa0, w.x, sf0l); sf0h = fma2_(pa0, w.y, sf0h);
            sf1l = fma2_(pa1, w.x, sf1l); sf1h = fma2_(pa1, w.y, sf1h);
        }

        // message = (value + edge_val) * ex * sf
        u64t pex0 = pk2(ex0, ex0);
        u64t pex1 = pk2(ex1, ex1);
        u64t m0l = mul2_(mul2_(add2_(v0.x, ev0l), sf0l), pex0);
        u64t m0h = mul2_(mul2_(add2_(v0.y, ev0h), sf0h), pex0);
        u64t m1l = mul2_(mul2_(add2_(v1.x, ev1l), sf1l), pex1);
        u64t m1h = mul2_(mul2_(add2_(v1.y, ev1h), sf1h), pex1);
        float4 m0, m1;
        up2(m0.x, m0.y, m0l); up2(m0.z, m0.w, m0h);
        up2(m1.x, m1.y, m1l); up2(m1.z, m1.w, m1h);
        atomicAdd((float4*)(g_aggr + (size_t)d0 * 128 + 4 * lane), m0);
        atomicAdd((float4*)(g_aggr + (size_t)d1 * 128 + 4 * lane), m1);
    }
}

// ---------------- K3: normalize + add skip ----------------
__global__ __launch_bounds__(256)
void finalize_kernel(float* __restrict__ out)
{
    int t = blockIdx.x * blockDim.x + threadIdx.x;
    if (t >= NN * 32) return;
    int n = t >> 5;
    int g = t & 31;
    float d = g_denom[n * 4 + (g >> 3)];
    float inv = (d > 0.f) ? 1.0f / d : 0.f;
    float4 a = *(const float4*)(g_aggr + n * 128 + 4 * g);
    float4 o = *(const float4*)(out + n * 128 + 4 * g);
    o.x = fmaf(a.x, inv, o.x);
    o.y = fmaf(a.y, inv, o.y);
    o.z = fmaf(a.z, inv, o.z);
    o.w = fmaf(a.w, inv, o.w);
    *(float4*)(out + n * 128 + 4 * g) = o;
}

// ---------------- host ----------------
extern "C" void kernel_launch(void* const* d_in, const int* in_sizes, int n_in,
                              void* d_out, int out_size)
{
    const float* x         = (const float*)d_in[0];
    const float* edge_attr = (const float*)d_in[1];
    const float* rbf       = (const float*)d_in[2];
    const float* sbf       = (const float*)d_in[3];
    const float* w_rbf0    = (const float*)d_in[4];
    const float* w_rbf1    = (const float*)d_in[5];
    const float* w_sbf0    = (const float*)d_in[6];
    const float* w_sbf1    = (const float*)d_in[7];
    const float* w_ek      = (const float*)d_in[8];
    const float* w_ev      = (const float*)d_in[9];
    const float* w_k       = (const float*)d_in[10];
    const float* b_k       = (const float*)d_in[11];
    const float* w_q       = (const float*)d_in[12];
    const float* b_q       = (const float*)d_in[13];
    const float* w_v       = (const float*)d_in[14];
    const float* b_v       = (const float*)d_in[15];
    const float* w_skip    = (const float*)d_in[16];
    const float* b_skip    = (const float*)d_in[17];
    const int*   ei        = (const int*)d_in[18];
    float* out = (float*)d_out;

    void *p_aggr, *p_denom;
    cudaGetSymbolAddress(&p_aggr, g_aggr);
    cudaGetSymbolAddress(&p_denom, g_denom);
    cudaMemsetAsync(p_aggr, 0, (size_t)NN * 128 * sizeof(float));   // launch 1
    cudaMemsetAsync(p_denom, 0, (size_t)NN * 4 * sizeof(float));    // launch 2

    combine_weights_kernel<<<6, 256>>>(w_rbf0, w_rbf1, w_sbf0, w_sbf1);  // launch 3

    int smem = 20288 * (int)sizeof(float);  // 81152 B -> 2 CTA/SM
    cudaFuncSetAttribute(node_kernel, cudaFuncAttributeMaxDynamicSharedMemorySize, smem);
    node_kernel<<<296, 256, smem>>>(x, rbf, w_ek, w_k, b_k, w_q, b_q,
                                    w_v, b_v, w_skip, b_skip, out);       // launch 4

    profile_align_kernel<<<1, 32>>>();                                    // launch 5

    edge_kernel<<<296, 256>>>(edge_attr, sbf, w_ev, ei);                  // launch 6 <- ncu -s 5

    finalize_kernel<<<(NN * 32 + 255) / 256, 256>>>(out);                 // launch 7
}